// round 4
// baseline (speedup 1.0000x reference)
#include <cuda_runtime.h>
#include <cstdint>

#define SEQ    512
#define BATCH  512
#define IN_DIM 128
#define NQ     8
#define D_TOT  136   // IN_DIM + NQ

// Scratch: Zx[s][b][o], o = g*8 + q
__device__ float g_zx[(size_t)SEQ * BATCH * 32];

typedef unsigned long long ull;

// --- packed fp32x2 ops (Blackwell; PTX-only) ---
__device__ __forceinline__ ull fma2(ull a, ull b, ull c) {
    ull d; asm("fma.rn.f32x2 %0, %1, %2, %3;" : "=l"(d) : "l"(a), "l"(b), "l"(c)); return d;
}
__device__ __forceinline__ ull mul2(ull a, ull b) {
    ull d; asm("mul.rn.f32x2 %0, %1, %2;" : "=l"(d) : "l"(a), "l"(b)); return d;
}
__device__ __forceinline__ ull add2(ull a, ull b) {
    ull d; asm("add.rn.f32x2 %0, %1, %2;" : "=l"(d) : "l"(a), "l"(b)); return d;
}
__device__ __forceinline__ ull pack2(float lo, float hi) {
    ull d; asm("mov.b64 %0, {%1, %2};" : "=l"(d) : "r"(__float_as_uint(lo)), "r"(__float_as_uint(hi))); return d;
}
__device__ __forceinline__ void unpack2(ull v, float& lo, float& hi) {
    unsigned a, b; asm("mov.b64 {%0, %1}, %2;" : "=r"(a), "=r"(b) : "l"(v));
    lo = __uint_as_float(a); hi = __uint_as_float(b);
}
__device__ __forceinline__ ull dup2(float x) {
    ull d; unsigned u = __float_as_uint(x);
    asm("mov.b64 %0, {%1, %1};" : "=l"(d) : "r"(u)); return d;
}
__device__ __forceinline__ float rcp_fast(float x) {
    float r; asm("rcp.approx.f32 %0, %1;" : "=f"(r) : "f"(x)); return r;
}

// ============================================================================
// Kernel 1: Zx[row][o] = sum_d x[row][d] * W[o][d] + b[o] + qp[o]  (unchanged)
// ============================================================================
__global__ __launch_bounds__(256) void zx_kernel(
    const float* __restrict__ x, const float* __restrict__ W,
    const float* __restrict__ b, const float* __restrict__ qp)
{
    __shared__ ulonglong2 Ws[IN_DIM * 4];
    __shared__ ulonglong2 Ws_hi[IN_DIM * 4];
    __shared__ float bias[32];

    int tid = threadIdx.x;
    float* WsF   = (float*)Ws;
    float* WsFhi = (float*)Ws_hi;
    for (int i = tid; i < IN_DIM * 32; i += 256) {
        int d = i >> 5, o = i & 31;
        float w = W[o * D_TOT + d];
        if (o < 16) WsF[d * 16 + o] = w;
        else        WsFhi[d * 16 + (o - 16)] = w;
    }
    if (tid < 32) bias[tid] = b[tid] + qp[tid];
    __syncthreads();

    int row = blockIdx.x * 256 + tid;
    const float4* xr = (const float4*)(x + (size_t)row * IN_DIM);

    ull acc[16];
#pragma unroll
    for (int i = 0; i < 16; i++) acc[i] = 0ULL;

#pragma unroll 4
    for (int d4 = 0; d4 < IN_DIM / 4; d4++) {
        float4 xv = xr[d4];
        float xs[4] = {xv.x, xv.y, xv.z, xv.w};
#pragma unroll
        for (int k = 0; k < 4; k++) {
            int d = d4 * 4 + k;
            ull xdd = dup2(xs[k]);
            const ulonglong2* wlo = Ws    + d * 4;
            const ulonglong2* whi = Ws_hi + d * 4;
#pragma unroll
            for (int j = 0; j < 4; j++) {
                ulonglong2 wp = wlo[j];
                acc[2 * j]     = fma2(xdd, wp.x, acc[2 * j]);
                acc[2 * j + 1] = fma2(xdd, wp.y, acc[2 * j + 1]);
            }
#pragma unroll
            for (int j = 0; j < 4; j++) {
                ulonglong2 wp = whi[j];
                acc[8 + 2 * j]     = fma2(xdd, wp.x, acc[8 + 2 * j]);
                acc[8 + 2 * j + 1] = fma2(xdd, wp.y, acc[8 + 2 * j + 1]);
            }
        }
    }

    float outv[32];
#pragma unroll
    for (int j = 0; j < 16; j++) {
        outv[2 * j]     = __uint_as_float((unsigned)(acc[j] & 0xffffffffu)) + bias[2 * j];
        outv[2 * j + 1] = __uint_as_float((unsigned)(acc[j] >> 32))         + bias[2 * j + 1];
    }
    float4* zr = (float4*)(g_zx + (size_t)row * 32);
#pragma unroll
    for (int j = 0; j < 8; j++)
        zr[j] = make_float4(outv[4 * j], outv[4 * j + 1], outv[4 * j + 2], outv[4 * j + 3]);
}

// ============================================================================
// Kernel 2: recurrence. 4 LANES PER BATCH (lane%4 = gate), 8 batches/warp.
//   Lane-local: dot (packed fma2), cos x8, cumprod (local!), CF4 tanh packed.
//   Cross-lane: 4x4 packet transpose (bfly, 8 SHFL) + h broadcast (8 SHFL).
// ============================================================================
__global__ void __launch_bounds__(32, 1) rnn_kernel(
    const float* __restrict__ W, const float* __restrict__ h0,
    const float* __restrict__ c0, float* __restrict__ out)
{
    const unsigned FULL = 0xffffffffu;
    int lane = threadIdx.x;          // 0..31
    int g    = lane & 3;             // gate
    int bl   = lane >> 2;            // batch within warp 0..7
    int b    = blockIdx.x * 8 + bl;  // batch 0..511

    // Wh2[j][qp] = (W[(g*8+2qp)][128+j], W[(g*8+2qp+1)][128+j]) packed
    ull Wh2[8][4];
#pragma unroll
    for (int qp = 0; qp < 4; qp++)
#pragma unroll
        for (int j = 0; j < 8; j++) {
            float w0 = W[(g * 8 + 2 * qp)     * D_TOT + IN_DIM + j];
            float w1 = W[(g * 8 + 2 * qp + 1) * D_TOT + IN_DIM + j];
            Wh2[j][qp] = pack2(w0, w1);
        }

    ull hd[8];
#pragma unroll
    for (int j = 0; j < 8; j++) hd[j] = dup2(h0[b * 8 + j]);
    float2 cc = *(const float2*)(c0 + b * 8 + 2 * g);
    float cA = cc.x, cB = cc.y;

    const float asc   = (g == 2) ? 1.0f : 0.5f;
    const float obias = (g == 2) ? 0.0f : 0.5f;
    const ull asc2 = dup2(asc);

    // CF4 tanh consts (gates, |x|<=1): x(105+10t)/(105+45t+t^2)
    const ull C10  = dup2(10.0f),  C45  = dup2(45.0f),  C105 = dup2(105.0f);
    // Pade [5/4] consts (cell, |c|<=2.1): x(t^2+105t+945)/(15t^2+420t+945)
    const ull C15  = dup2(15.0f),  C420 = dup2(420.0f), C945 = dup2(945.0f);

    const float4* zp = (const float4*)g_zx + ((size_t)b * 8 + g * 2);
    const size_t Z4STRIDE = (size_t)BATCH * 8;    // float4 per timestep

    float4 zb[4][2];
#pragma unroll
    for (int u = 0; u < 4; u++) {
        zb[u][0] = zp[(size_t)u * Z4STRIDE];
        zb[u][1] = zp[(size_t)u * Z4STRIDE + 1];
    }

    float2* op = (float2*)(out + (size_t)b * 8 + 2 * g);
    const size_t O2STRIDE = (size_t)BATCH * 4;    // float2 per timestep

    float hA = 0.0f, hB = 0.0f;

    for (int s = 0; s < SEQ; s += 4) {
#pragma unroll
        for (int u = 0; u < 4; u++) {
            int sp = s + u + 4; sp = sp < SEQ ? sp : SEQ - 1;
            float4 zn0 = zp[(size_t)sp * Z4STRIDE];
            float4 zn1 = zp[(size_t)sp * Z4STRIDE + 1];

            // z[q] = zx[q] + h . Wh[q], packed over q-pairs
            ull acc0 = pack2(zb[u][0].x, zb[u][0].y);
            ull acc1 = pack2(zb[u][0].z, zb[u][0].w);
            ull acc2 = pack2(zb[u][1].x, zb[u][1].y);
            ull acc3 = pack2(zb[u][1].z, zb[u][1].w);
#pragma unroll
            for (int j = 0; j < 8; j++) {
                acc0 = fma2(hd[j], Wh2[j][0], acc0);
                acc1 = fma2(hd[j], Wh2[j][1], acc1);
                acc2 = fma2(hd[j], Wh2[j][2], acc2);
                acc3 = fma2(hd[j], Wh2[j][3], acc3);
            }
            float a[8];
            unpack2(acc0, a[0], a[1]);
            unpack2(acc1, a[2], a[3]);
            unpack2(acc2, a[4], a[5]);
            unpack2(acc3, a[6], a[7]);
#pragma unroll
            for (int q = 0; q < 8; q++) a[q] = __cosf(a[q]);

            // lane-local inclusive cumprod (Sklansky, depth 3)
            a[1] *= a[0]; a[3] *= a[2]; a[5] *= a[4]; a[7] *= a[6];
            a[2] *= a[1]; a[3] *= a[1]; a[6] *= a[5]; a[7] *= a[5];
            a[4] *= a[3]; a[5] *= a[3]; a[6] *= a[3]; a[7] *= a[3];

            // gate value per q-pair: v = obias + asc*tanh(asc*prod), CF4
            ull V[4];
#pragma unroll
            for (int qp = 0; qp < 4; qp++) {
                ull X  = mul2(asc2, pack2(a[2 * qp], a[2 * qp + 1]));
                ull T  = mul2(X, X);
                ull An = fma2(C10, T, C105);
                ull Bd = fma2(add2(T, C45), T, C105);
                ull N  = mul2(X, An);
                float d0, d1, n0, n1;
                unpack2(Bd, d0, d1);
                unpack2(N, n0, n1);
                float inv = rcp_fast(d0 * d1);
                float v0 = fmaf(asc, (n0 * d1) * inv, obias);
                float v1 = fmaf(asc, (n1 * d0) * inv, obias);
                V[qp] = pack2(v0, v1);
            }

            // 4x4 packet transpose within quad (butterfly, 2 stages)
            bool bt0 = (g & 1), bt1 = (g & 2);
            ull sx0 = bt0 ? V[0] : V[1];
            ull rx0 = __shfl_xor_sync(FULL, sx0, 1);
            ull sx1 = bt0 ? V[2] : V[3];
            ull rx1 = __shfl_xor_sync(FULL, sx1, 1);
            ull W0 = bt0 ? rx0 : V[0];
            ull W1 = bt0 ? V[1] : rx0;
            ull W2 = bt0 ? rx1 : V[2];
            ull W3 = bt0 ? V[3] : rx1;
            ull sy0 = bt1 ? W0 : W2;
            ull ry0 = __shfl_xor_sync(FULL, sy0, 2);
            ull sy1 = bt1 ? W1 : W3;
            ull ry1 = __shfl_xor_sync(FULL, sy1, 2);
            ull A0 = bt1 ? ry0 : W0;   // forget pair for q = 2g, 2g+1
            ull A1 = bt1 ? ry1 : W1;   // input
            ull A2 = bt1 ? W2 : ry0;   // update
            ull A3 = bt1 ? W3 : ry1;   // output

            float f0, f1, i0, i1, g0, g1, o0, o1;
            unpack2(A0, f0, f1);
            unpack2(A1, i0, i1);
            unpack2(A2, g0, g1);
            unpack2(A3, o0, o1);

            cA = fmaf(f0, cA, i0 * g0);
            cB = fmaf(f1, cB, i1 * g1);

            // tanh(c): Pade [5/4], packed pair, single rcp
            ull C  = pack2(cA, cB);
            ull T2 = mul2(C, C);
            ull An2 = fma2(add2(T2, C105), T2, C945);
            ull Bd2 = fma2(fma2(C15, T2, C420), T2, C945);
            ull N2  = mul2(C, An2);
            float e0, e1, m0, m1;
            unpack2(Bd2, e0, e1);
            unpack2(N2, m0, m1);
            float inv2 = rcp_fast(e0 * e1);
            hA = o0 * ((m0 * e1) * inv2);
            hB = o1 * ((m1 * e0) * inv2);

            *op = make_float2(hA, hB);
            op += O2STRIDE;

            // broadcast h across the quad (8 scalar shfl, width 4)
#pragma unroll
            for (int k = 0; k < 4; k++) {
                hd[2 * k]     = dup2(__shfl_sync(FULL, hA, k, 4));
                hd[2 * k + 1] = dup2(__shfl_sync(FULL, hB, k, 4));
            }

            zb[u][0] = zn0;
            zb[u][1] = zn1;
        }
    }

    // Final states: h_f then c_f (each lane owns q = 2g, 2g+1)
    size_t base = (size_t)SEQ * BATCH * 8;
    *(float2*)(out + base + (size_t)b * 8 + 2 * g)             = make_float2(hA, hB);
    *(float2*)(out + base + BATCH * 8 + (size_t)b * 8 + 2 * g) = make_float2(cA, cB);
}

extern "C" void kernel_launch(void* const* d_in, const int* in_sizes, int n_in,
                              void* d_out, int out_size) {
    const float* x  = (const float*)d_in[0];   // inputs (512,512,128)
    const float* h0 = (const float*)d_in[1];   // (512,8)
    const float* c0 = (const float*)d_in[2];   // (512,8)
    const float* W  = (const float*)d_in[3];   // (4,8,136)
    const float* b  = (const float*)d_in[4];   // (4,8)
    const float* qp = (const float*)d_in[5];   // (4,8)
    float* out = (float*)d_out;

    zx_kernel<<<(SEQ * BATCH) / 256, 256>>>(x, W, b, qp);
    rnn_kernel<<<BATCH / 8, 32>>>(W, h0, c0, out);
}

// round 5
// speedup vs baseline: 1.2213x; 1.2213x over previous
#include <cuda_runtime.h>
#include <cstdint>

#define SEQ    512
#define BATCH  512
#define IN_DIM 128
#define NQ     8
#define D_TOT  136   // IN_DIM + NQ

// Scratch: Zx[s][b][o], o = g*8 + q
__device__ float g_zx[(size_t)SEQ * BATCH * 32];

typedef unsigned long long ull;

// --- packed fp32x2 ops (Blackwell; PTX-only) ---
__device__ __forceinline__ ull fma2(ull a, ull b, ull c) {
    ull d; asm("fma.rn.f32x2 %0, %1, %2, %3;" : "=l"(d) : "l"(a), "l"(b), "l"(c)); return d;
}
__device__ __forceinline__ ull mul2(ull a, ull b) {
    ull d; asm("mul.rn.f32x2 %0, %1, %2;" : "=l"(d) : "l"(a), "l"(b)); return d;
}
__device__ __forceinline__ ull add2(ull a, ull b) {
    ull d; asm("add.rn.f32x2 %0, %1, %2;" : "=l"(d) : "l"(a), "l"(b)); return d;
}
__device__ __forceinline__ ull pack2(float lo, float hi) {
    ull d; asm("mov.b64 %0, {%1, %2};" : "=l"(d) : "r"(__float_as_uint(lo)), "r"(__float_as_uint(hi))); return d;
}
__device__ __forceinline__ void unpack2(ull v, float& lo, float& hi) {
    unsigned a, b; asm("mov.b64 {%0, %1}, %2;" : "=r"(a), "=r"(b) : "l"(v));
    lo = __uint_as_float(a); hi = __uint_as_float(b);
}
__device__ __forceinline__ ull dup2(float x) {
    ull d; unsigned u = __float_as_uint(x);
    asm("mov.b64 %0, {%1, %1};" : "=l"(d) : "r"(u)); return d;
}
__device__ __forceinline__ float rcp_fast(float x) {
    float r; asm("rcp.approx.f32 %0, %1;" : "=f"(r) : "f"(x)); return r;
}

// ============================================================================
// Kernel 1: Zx[row][o] = sum_d x[row][d] * W[o][d] + b[o] + qp[o]
//   TWO rows per thread: each broadcast-LDS'd W packet feeds 32 fma2.
// ============================================================================
__global__ __launch_bounds__(256) void zx_kernel(
    const float* __restrict__ x, const float* __restrict__ W,
    const float* __restrict__ b, const float* __restrict__ qp)
{
    __shared__ ulonglong2 Ws[IN_DIM * 4];     // outputs 0..15 of each d
    __shared__ ulonglong2 Ws_hi[IN_DIM * 4];  // outputs 16..31 of each d
    __shared__ float bias[32];

    int tid = threadIdx.x;
    float* WsF   = (float*)Ws;
    float* WsFhi = (float*)Ws_hi;
    for (int i = tid; i < IN_DIM * 32; i += 256) {
        int d = i >> 5, o = i & 31;
        float w = W[o * D_TOT + d];
        if (o < 16) WsF[d * 16 + o] = w;
        else        WsFhi[d * 16 + (o - 16)] = w;
    }
    if (tid < 32) bias[tid] = b[tid] + qp[tid];
    __syncthreads();

    int row0 = blockIdx.x * 512 + tid;
    int row1 = row0 + 256;
    const float4* xr0 = (const float4*)(x + (size_t)row0 * IN_DIM);
    const float4* xr1 = (const float4*)(x + (size_t)row1 * IN_DIM);

    ull acc0[16], acc1[16];
#pragma unroll
    for (int i = 0; i < 16; i++) { acc0[i] = 0ULL; acc1[i] = 0ULL; }

#pragma unroll 2
    for (int d4 = 0; d4 < IN_DIM / 4; d4++) {
        float4 xv0 = xr0[d4];
        float4 xv1 = xr1[d4];
        float xs0[4] = {xv0.x, xv0.y, xv0.z, xv0.w};
        float xs1[4] = {xv1.x, xv1.y, xv1.z, xv1.w};
#pragma unroll
        for (int k = 0; k < 4; k++) {
            int d = d4 * 4 + k;
            ull xa = dup2(xs0[k]);
            ull xb = dup2(xs1[k]);
            const ulonglong2* wlo = Ws    + d * 4;
            const ulonglong2* whi = Ws_hi + d * 4;
#pragma unroll
            for (int j = 0; j < 4; j++) {
                ulonglong2 wp = wlo[j];
                acc0[2 * j]     = fma2(xa, wp.x, acc0[2 * j]);
                acc0[2 * j + 1] = fma2(xa, wp.y, acc0[2 * j + 1]);
                acc1[2 * j]     = fma2(xb, wp.x, acc1[2 * j]);
                acc1[2 * j + 1] = fma2(xb, wp.y, acc1[2 * j + 1]);
            }
#pragma unroll
            for (int j = 0; j < 4; j++) {
                ulonglong2 wp = whi[j];
                acc0[8 + 2 * j]     = fma2(xa, wp.x, acc0[8 + 2 * j]);
                acc0[8 + 2 * j + 1] = fma2(xa, wp.y, acc0[8 + 2 * j + 1]);
                acc1[8 + 2 * j]     = fma2(xb, wp.x, acc1[8 + 2 * j]);
                acc1[8 + 2 * j + 1] = fma2(xb, wp.y, acc1[8 + 2 * j + 1]);
            }
        }
    }

    float4* zr0 = (float4*)(g_zx + (size_t)row0 * 32);
    float4* zr1 = (float4*)(g_zx + (size_t)row1 * 32);
#pragma unroll
    for (int j = 0; j < 8; j++) {
        float e0, e1, e2, e3;
        unpack2(acc0[2 * j], e0, e1); unpack2(acc0[2 * j + 1], e2, e3);
        zr0[j] = make_float4(e0 + bias[4 * j], e1 + bias[4 * j + 1],
                             e2 + bias[4 * j + 2], e3 + bias[4 * j + 3]);
        unpack2(acc1[2 * j], e0, e1); unpack2(acc1[2 * j + 1], e2, e3);
        zr1[j] = make_float4(e0 + bias[4 * j], e1 + bias[4 * j + 1],
                             e2 + bias[4 * j + 2], e3 + bias[4 * j + 3]);
    }
}

// ============================================================================
// Kernel 2: recurrence. 8 LANES PER BATCH: lane = bl*8 + g*2 + hf.
//   Lane: gate g, q-half hf (4 q's). smem for gate transpose + h broadcast.
// ============================================================================
__global__ void __launch_bounds__(128, 1) rnn_kernel(
    const float* __restrict__ W, const float* __restrict__ h0,
    const float* __restrict__ c0, float* __restrict__ out)
{
    __shared__ __align__(16) char sm[4 * 896];   // per warp: 576B Vbuf + 320B Hbuf

    const unsigned FULL = 0xffffffffu;
    int tid  = threadIdx.x;
    int lane = tid & 31, w = tid >> 5;
    int hf = lane & 1;
    int g  = (lane >> 1) & 3;
    int bl = lane >> 3;                       // batch within warp
    int b  = blockIdx.x * 16 + w * 4 + bl;    // batch 0..511
    int p  = ((g & 1) << 1) | hf;             // owned q-pair 0..3
    bool owner = (g < 2);

    char* smV = sm + w * 896;
    char* smH = sm + w * 896 + 576;
    char* vw  = smV + bl * 144 + hf * 64 + g * 16;               // V write (16B)
    char* vrd = smV + bl * 144 + (p >> 1) * 64 + (p & 1) * 8;    // V read base
    char* hw  = smH + bl * 80 + p * 16;                          // H write (16B)
    char* hrd = smH + bl * 80;                                   // H read base

    // Wh2[j][t]: W rows (g*8+4hf+2t, +1), col 128+j, packed
    ull Wh2[8][2];
#pragma unroll
    for (int t = 0; t < 2; t++)
#pragma unroll
        for (int j = 0; j < 8; j++) {
            float w0 = W[(g * 8 + 4 * hf + 2 * t)     * D_TOT + IN_DIM + j];
            float w1 = W[(g * 8 + 4 * hf + 2 * t + 1) * D_TOT + IN_DIM + j];
            Wh2[j][t] = pack2(w0, w1);
        }

    ull hd[8];
#pragma unroll
    for (int j = 0; j < 8; j++) hd[j] = dup2(h0[b * 8 + j]);
    ull Cp = pack2(c0[b * 8 + 2 * p], c0[b * 8 + 2 * p + 1]);

    const float asc   = (g == 2) ? 1.0f : 0.5f;
    const float obias = (g == 2) ? 0.0f : 0.5f;
    const ull asc2 = dup2(asc);
    // CF4 tanh (gates, |x|<=1): x(105+10t)/(105+45t+t^2)
    const ull C10 = dup2(10.0f), C45 = dup2(45.0f), C105 = dup2(105.0f);
    // Pade [5/4] (cell, |c|<=2.1): x(t^2+105t+945)/(15t^2+420t+945)
    const ull C15 = dup2(15.0f), C420 = dup2(420.0f), C945 = dup2(945.0f);

    // zx: float4 per lane = gate g, q 4hf..4hf+3
    const float4* zp = (const float4*)g_zx + ((size_t)b * 8 + g * 2 + hf);
    const size_t Z4STRIDE = (size_t)BATCH * 8;

    float4 zb[4];
#pragma unroll
    for (int u = 0; u < 4; u++) zb[u] = zp[(size_t)u * Z4STRIDE];

    float2* op2 = (float2*)(out + (size_t)b * 8 + 2 * p);
    const size_t O2STRIDE = (size_t)BATCH * 4;

    float hA = 0.0f, hB = 0.0f;

    for (int s = 0; s < SEQ; s += 4) {
#pragma unroll
        for (int u = 0; u < 4; u++) {
            int sp = s + u + 4; sp = sp < SEQ ? sp : SEQ - 1;
            float4 zn = zp[(size_t)sp * Z4STRIDE];

            // dot: 2 packed accumulators over 8 h
            ull acc0 = pack2(zb[u].x, zb[u].y);
            ull acc1 = pack2(zb[u].z, zb[u].w);
#pragma unroll
            for (int j = 0; j < 8; j++) {
                acc0 = fma2(hd[j], Wh2[j][0], acc0);
                acc1 = fma2(hd[j], Wh2[j][1], acc1);
            }
            float a0, a1, a2, a3;
            unpack2(acc0, a0, a1);
            unpack2(acc1, a2, a3);
            a0 = __cosf(a0); a1 = __cosf(a1); a2 = __cosf(a2); a3 = __cosf(a3);

            // local inclusive cumprod of 4
            float k0 = a0;
            float k1 = a0 * a1;
            float t23 = a2 * a3;
            float k2 = k1 * a2;
            float k3 = k1 * t23;

            // cross-half prefix (hf=1 multiplies by hf=0's total)
            float T = __shfl_xor_sync(FULL, k3, 1);
            ull M = dup2(hf ? T : 1.0f);
            ull X0 = mul2(mul2(M, pack2(k0, k1)), asc2);
            ull X1 = mul2(mul2(M, pack2(k2, k3)), asc2);

            // CF4 rationals, single rcp for all 4 denominators
            ull T0 = mul2(X0, X0), T1 = mul2(X1, X1);
            ull N0 = mul2(X0, fma2(C10, T0, C105));
            ull N1 = mul2(X1, fma2(C10, T1, C105));
            ull B0 = fma2(add2(T0, C45), T0, C105);
            ull B1 = fma2(add2(T1, C45), T1, C105);
            float d0, d1, d2, d3, n0, n1, n2, n3;
            unpack2(B0, d0, d1); unpack2(B1, d2, d3);
            unpack2(N0, n0, n1); unpack2(N1, n2, n3);
            float d01 = d0 * d1, d23 = d2 * d3;
            float inv = rcp_fast(d01 * d23);
            float v0 = fmaf(asc, n0 * (d1 * d23) * inv, obias);
            float v1 = fmaf(asc, n1 * (d0 * d23) * inv, obias);
            float v2 = fmaf(asc, n2 * (d3 * d01) * inv, obias);
            float v3 = fmaf(asc, n3 * (d2 * d01) * inv, obias);

            // gate transpose via smem
            ulonglong2 vpk; vpk.x = pack2(v0, v1); vpk.y = pack2(v2, v3);
            *(ulonglong2*)vw = vpk;
            __syncwarp(FULL);
            ull Fp = *(const ull*)(vrd);
            ull Ip = *(const ull*)(vrd + 16);
            ull Gp = *(const ull*)(vrd + 32);
            ull Op = *(const ull*)(vrd + 48);

            // c update + cell tanh (packed pair, 1 rcp)
            Cp = fma2(Fp, Cp, mul2(Ip, Gp));
            ull TC = mul2(Cp, Cp);
            ull NC = mul2(Cp, fma2(add2(TC, C105), TC, C945));
            ull BC = fma2(fma2(C15, TC, C420), TC, C945);
            float e0, e1, m0, m1, o0, o1;
            unpack2(BC, e0, e1);
            unpack2(NC, m0, m1);
            unpack2(Op, o0, o1);
            float inv2 = rcp_fast(e0 * e1);
            hA = o0 * ((m0 * e1) * inv2);
            hB = o1 * ((m1 * e0) * inv2);

            // h broadcast via smem (duplicated pairs, single writer)
            if (owner) {
                ulonglong2 hpk; hpk.x = dup2(hA); hpk.y = dup2(hB);
                *(ulonglong2*)hw = hpk;
            }
            __syncwarp(FULL);
#pragma unroll
            for (int k = 0; k < 4; k++) {
                ulonglong2 hp = *(const ulonglong2*)(hrd + k * 16);
                hd[2 * k] = hp.x; hd[2 * k + 1] = hp.y;
            }

            if (owner) *op2 = make_float2(hA, hB);
            op2 += O2STRIDE;

            zb[u] = zn;
        }
    }

    // Final states: h_f then c_f (owner writes its q-pair)
    size_t base = (size_t)SEQ * BATCH * 8;
    if (owner) {
        float cA, cB; unpack2(Cp, cA, cB);
        *(float2*)(out + base + (size_t)b * 8 + 2 * p)             = make_float2(hA, hB);
        *(float2*)(out + base + BATCH * 8 + (size_t)b * 8 + 2 * p) = make_float2(cA, cB);
    }
}

extern "C" void kernel_launch(void* const* d_in, const int* in_sizes, int n_in,
                              void* d_out, int out_size) {
    const float* x  = (const float*)d_in[0];   // inputs (512,512,128)
    const float* h0 = (const float*)d_in[1];   // (512,8)
    const float* c0 = (const float*)d_in[2];   // (512,8)
    const float* W  = (const float*)d_in[3];   // (4,8,136)
    const float* b  = (const float*)d_in[4];   // (4,8)
    const float* qp = (const float*)d_in[5];   // (4,8)
    float* out = (float*)d_out;

    zx_kernel<<<(SEQ * BATCH) / 512, 256>>>(x, W, b, qp);
    rnn_kernel<<<BATCH / 16, 128>>>(W, h0, c0, out);
}